// round 2
// baseline (speedup 1.0000x reference)
#include <cuda_runtime.h>

#define BATCH 2048
#define NPTS  4095
#define TPB   1024
#define EPT   4
#define PADN  4096

__device__ float g_partial[BATCH];
__device__ int   g_count = 0;

// dynamic smem: ssx[4096] ssy[4096] ssz[4096] wsx[32] wsy[32] wsz[32] red[32]
#define SMEM_FLOATS (3 * PADN + 4 * 32)
#define SMEM_BYTES  (SMEM_FLOATS * 4)

extern __shared__ __align__(16) float smem_dyn[];

__global__ __launch_bounds__(TPB)
void mpd_fused_kernel(const float* __restrict__ o3,
                      const float* __restrict__ s3,
                      const float* __restrict__ o2,
                      const float* __restrict__ s2,
                      const float* __restrict__ df,
                      float* __restrict__ out)
{
    float* ssx = smem_dyn;
    float* ssy = smem_dyn + PADN;
    float* ssz = smem_dyn + 2 * PADN;
    float* wsx = smem_dyn + 3 * PADN;
    float* wsy = wsx + 32;
    float* wsz = wsy + 32;
    float* red = wsz + 32;
    __shared__ int is_last;

    const int b = blockIdx.x;
    const int t = threadIdx.x;
    const unsigned lane = t & 31u;
    const unsigned warp = t >> 5;

    const float* __restrict__ r3p  = s3 + (size_t)(b * 3 + 0) * NPTS;
    const float* __restrict__ th3p = s3 + (size_t)(b * 3 + 1) * NPTS;
    const float* __restrict__ ph3p = s3 + (size_t)(b * 3 + 2) * NPTS;
    const float* __restrict__ r2p  = s2 + (size_t)(b * 3 + 0) * NPTS;
    const float* __restrict__ th2p = s2 + (size_t)(b * 3 + 1) * NPTS;
    const float* __restrict__ ph2p = s2 + (size_t)(b * 3 + 2) * NPTS;
    const float* __restrict__ dthp = df + (size_t)(b * 2 + 0) * NPTS;
    const float* __restrict__ dphp = df + (size_t)(b * 2 + 1) * NPTS;

    const float dx = o3[b * 3 + 0] - o2[b * 3 + 0];
    const float dy = o3[b * 3 + 1] - o2[b * 3 + 1];
    const float dz = o3[b * 3 + 2] - o2[b * 3 + 2];

    // ---- Phase A: CYCLIC (coalesced) computation of s_i, staged to smem ----
    #pragma unroll
    for (int k = 0; k < EPT; k++) {
        const int i = t + k * TPB;           // lane stride 4B: fully coalesced
        float vx = 0.f, vy = 0.f, vz = 0.f;
        if (i < NPTS) {
            float r3  = r3p[i];
            float th3 = th3p[i] + dthp[i];
            float ph3 = ph3p[i] + dphp[i];
            float st, ct, sp, cp;
            __sincosf(th3, &st, &ct);
            __sincosf(ph3, &sp, &cp);
            float rst = r3 * st;
            vx = rst * cp; vy = rst * sp; vz = r3 * ct;

            float r2  = r2p[i];
            float th2 = th2p[i];
            float ph2 = ph2p[i];
            __sincosf(th2, &st, &ct);
            __sincosf(ph2, &sp, &cp);
            rst = r2 * st;
            vx -= rst * cp; vy -= rst * sp; vz -= r2 * ct;
        }
        ssx[i] = vx; ssy[i] = vy; ssz[i] = vz;   // stride-1 stores: conflict-free
    }
    __syncthreads();

    // ---- Phase B: BLOCKED read via LDS.128 (conflict-free), local scan ----
    float4 X = *reinterpret_cast<const float4*>(ssx + 4 * t);
    float4 Y = *reinterpret_cast<const float4*>(ssy + 4 * t);
    float4 Z = *reinterpret_cast<const float4*>(ssz + 4 * t);

    float sx[EPT] = {X.x, X.y, X.z, X.w};
    float sy[EPT] = {Y.x, Y.y, Y.z, Y.w};
    float sz[EPT] = {Z.x, Z.y, Z.z, Z.w};

    #pragma unroll
    for (int k = 1; k < EPT; k++) {
        sx[k] += sx[k - 1];
        sy[k] += sy[k - 1];
        sz[k] += sz[k - 1];
    }
    const float tx = sx[EPT - 1], ty = sy[EPT - 1], tz = sz[EPT - 1];

    // warp inclusive scan of thread totals
    float ix = tx, iy = ty, iz = tz;
    #pragma unroll
    for (int o = 1; o < 32; o <<= 1) {
        float ax = __shfl_up_sync(0xFFFFFFFFu, ix, o);
        float ay = __shfl_up_sync(0xFFFFFFFFu, iy, o);
        float az = __shfl_up_sync(0xFFFFFFFFu, iz, o);
        if (lane >= (unsigned)o) { ix += ax; iy += ay; iz += az; }
    }

    // cross-warp scan
    __syncthreads();   // smem reuse safety: phase-B reads done before ws* writes? ws* disjoint from ss*, but keep ordering cheap
    if (lane == 31) { wsx[warp] = ix; wsy[warp] = iy; wsz[warp] = iz; }
    __syncthreads();
    if (warp == 0) {
        float vx = wsx[lane], vy = wsy[lane], vz = wsz[lane];
        #pragma unroll
        for (int o = 1; o < 32; o <<= 1) {
            float ax = __shfl_up_sync(0xFFFFFFFFu, vx, o);
            float ay = __shfl_up_sync(0xFFFFFFFFu, vy, o);
            float az = __shfl_up_sync(0xFFFFFFFFu, vz, o);
            if (lane >= (unsigned)o) { vx += ax; vy += ay; vz += az; }
        }
        wsx[lane] = vx; wsy[lane] = vy; wsz[lane] = vz;
    }
    __syncthreads();

    float offx = dx + (ix - tx);
    float offy = dy + (iy - ty);
    float offz = dz + (iz - tz);
    if (warp > 0) {
        offx += wsx[warp - 1];
        offy += wsy[warp - 1];
        offz += wsz[warp - 1];
    }

    // abs-sum over this thread's positions
    float acc = 0.f;
    if (t == 0) acc = fabsf(dx) + fabsf(dy) + fabsf(dz);   // j=0 (origin)
    const int base = 4 * t;
    #pragma unroll
    for (int k = 0; k < EPT; k++) {
        if (base + k < NPTS) {
            acc += fabsf(offx + sx[k]) + fabsf(offy + sy[k]) + fabsf(offz + sz[k]);
        }
    }

    // block reduce
    #pragma unroll
    for (int o = 16; o > 0; o >>= 1)
        acc += __shfl_down_sync(0xFFFFFFFFu, acc, o);
    if (lane == 0) red[warp] = acc;
    __syncthreads();
    if (warp == 0) {
        float a = red[lane];
        #pragma unroll
        for (int o = 16; o > 0; o >>= 1)
            a += __shfl_down_sync(0xFFFFFFFFu, a, o);
        if (lane == 0) g_partial[b] = a * (1.0f / (NPTS + 1));
    }

    // ---- last-block fused final reduction (deterministic) ----
    if (t == 0) {
        __threadfence();
        int ticket = atomicAdd(&g_count, 1);
        is_last = (ticket == gridDim.x - 1) ? 1 : 0;
    }
    __syncthreads();
    if (is_last) {
        float a = __ldcg(&g_partial[t]) + __ldcg(&g_partial[t + TPB]);
        #pragma unroll
        for (int o = 16; o > 0; o >>= 1)
            a += __shfl_down_sync(0xFFFFFFFFu, a, o);
        if (lane == 0) red[warp] = a;
        __syncthreads();
        if (warp == 0) {
            float v = red[lane];
            #pragma unroll
            for (int o = 16; o > 0; o >>= 1)
                v += __shfl_down_sync(0xFFFFFFFFu, v, o);
            if (lane == 0) {
                out[0] = v;
                atomicExch(&g_count, 0);   // reset for next graph replay
            }
        }
    }
}

extern "C" void kernel_launch(void* const* d_in, const int* in_sizes, int n_in,
                              void* d_out, int out_size)
{
    const float* o3 = (const float*)d_in[0];  // origin_3D        (B,3,1)
    const float* s3 = (const float*)d_in[1];  // spherical_3D     (B,3,N)
    const float* o2 = (const float*)d_in[2];  // origin_2D        (B,3,1)
    const float* s2 = (const float*)d_in[3];  // spherical_2D     (B,3,N)
    const float* df = (const float*)d_in[4];  // deformation_field(B,2,N)
    float* out = (float*)d_out;

    cudaFuncSetAttribute(mpd_fused_kernel,
                         cudaFuncAttributeMaxDynamicSharedMemorySize, SMEM_BYTES);
    mpd_fused_kernel<<<BATCH, TPB, SMEM_BYTES>>>(o3, s3, o2, s2, df, out);
}

// round 3
// speedup vs baseline: 1.2645x; 1.2645x over previous
#include <cuda_runtime.h>

#define BATCH  2048
#define NPTS   4095
#define TPB    1024
#define NCHUNK 4

__device__ float g_partial[BATCH];
__device__ int   g_count = 0;

__global__ void __launch_bounds__(TPB, 2)
mpd_fused_kernel(const float* __restrict__ o3,
                 const float* __restrict__ s3,
                 const float* __restrict__ o2,
                 const float* __restrict__ s2,
                 const float* __restrict__ df,
                 float* __restrict__ out)
{
    __shared__ float wsb[NCHUNK][3][32];   // per-chunk warp totals (x,y,z)
    __shared__ float red[32];
    __shared__ int   is_last;

    const int b = blockIdx.x;
    const int t = threadIdx.x;
    const unsigned lane = t & 31u;
    const unsigned warp = t >> 5;

    const float* __restrict__ s3b = s3 + (size_t)b * (3 * NPTS);
    const float* __restrict__ s2b = s2 + (size_t)b * (3 * NPTS);
    const float* __restrict__ dfb = df + (size_t)b * (2 * NPTS);

    // running offset = origin delta, accumulated chunk totals get added
    float offx = o3[b * 3 + 0] - o2[b * 3 + 0];
    float offy = o3[b * 3 + 1] - o2[b * 3 + 1];
    float offz = o3[b * 3 + 2] - o2[b * 3 + 2];

    float acc = 0.f;
    if (t == 0) acc = fabsf(offx) + fabsf(offy) + fabsf(offz);  // j=0 (origin)

    // ---- software-pipelined chunk loop: coalesced loads, chunk-wise scans ----
    float cr3, ct3, cp3, cr2, ct2, cp2, cdt, cdp;   // current chunk inputs
    float nr3, nt3, np3, nr2, nt2, np2, ndt, ndp;   // next chunk inputs

    {   // prefetch chunk 0 (i = t, always < NPTS)
        const int i = t;
        cr3 = s3b[i]; ct3 = s3b[i + NPTS]; cp3 = s3b[i + 2 * NPTS];
        cr2 = s2b[i]; ct2 = s2b[i + NPTS]; cp2 = s2b[i + 2 * NPTS];
        cdt = dfb[i]; cdp = dfb[i + NPTS];
    }

    #pragma unroll
    for (int k = 0; k < NCHUNK; k++) {
        // issue next chunk's loads early (overlap with scan barriers below)
        if (k < NCHUNK - 1) {
            const int i = t + (k + 1) * TPB;
            const bool ok = (i < NPTS);
            nr3 = ok ? s3b[i] : 0.f;
            nt3 = ok ? s3b[i + NPTS] : 0.f;
            np3 = ok ? s3b[i + 2 * NPTS] : 0.f;
            nr2 = ok ? s2b[i] : 0.f;
            nt2 = ok ? s2b[i + NPTS] : 0.f;
            np2 = ok ? s2b[i + 2 * NPTS] : 0.f;
            ndt = ok ? dfb[i] : 0.f;
            ndp = ok ? dfb[i + NPTS] : 0.f;
        }

        // shape3D - shape2D for this thread's element of chunk k
        float st, ct, sp, cp;
        __sincosf(ct3 + cdt, &st, &ct);
        __sincosf(cp3 + cdp, &sp, &cp);
        float rst = cr3 * st;
        float vx = rst * cp, vy = rst * sp, vz = cr3 * ct;
        __sincosf(ct2, &st, &ct);
        __sincosf(cp2, &sp, &cp);
        rst = cr2 * st;
        vx -= rst * cp; vy -= rst * sp; vz -= cr2 * ct;
        // (out-of-range threads loaded zeros -> v == 0, harmless in scan)

        // warp inclusive scan
        float ix = vx, iy = vy, iz = vz;
        #pragma unroll
        for (int o = 1; o < 32; o <<= 1) {
            float ax = __shfl_up_sync(0xFFFFFFFFu, ix, o);
            float ay = __shfl_up_sync(0xFFFFFFFFu, iy, o);
            float az = __shfl_up_sync(0xFFFFFFFFu, iz, o);
            if (lane >= (unsigned)o) { ix += ax; iy += ay; iz += az; }
        }
        if (lane == 31) {
            wsb[k][0][warp] = ix; wsb[k][1][warp] = iy; wsb[k][2][warp] = iz;
        }
        __syncthreads();
        if (warp == 0) {
            float ax = wsb[k][0][lane], ay = wsb[k][1][lane], az = wsb[k][2][lane];
            #pragma unroll
            for (int o = 1; o < 32; o <<= 1) {
                float bx = __shfl_up_sync(0xFFFFFFFFu, ax, o);
                float by = __shfl_up_sync(0xFFFFFFFFu, ay, o);
                float bz = __shfl_up_sync(0xFFFFFFFFu, az, o);
                if (lane >= (unsigned)o) { ax += bx; ay += by; az += bz; }
            }
            wsb[k][0][lane] = ax; wsb[k][1][lane] = ay; wsb[k][2][lane] = az;
        }
        __syncthreads();

        float px = ix, py = iy, pz = iz;             // block-inclusive prefix
        if (warp > 0) {
            px += wsb[k][0][warp - 1];
            py += wsb[k][1][warp - 1];
            pz += wsb[k][2][warp - 1];
        }

        if (t + k * TPB < NPTS) {
            acc += fabsf(offx + px) + fabsf(offy + py) + fabsf(offz + pz);
        }

        // advance offset by chunk total (uniform across block)
        offx += wsb[k][0][31];
        offy += wsb[k][1][31];
        offz += wsb[k][2][31];

        // rotate pipeline buffers
        cr3 = nr3; ct3 = nt3; cp3 = np3;
        cr2 = nr2; ct2 = nt2; cp2 = np2;
        cdt = ndt; cdp = ndp;
    }

    // ---- block reduce of acc ----
    #pragma unroll
    for (int o = 16; o > 0; o >>= 1)
        acc += __shfl_down_sync(0xFFFFFFFFu, acc, o);
    if (lane == 0) red[warp] = acc;
    __syncthreads();
    if (warp == 0) {
        float a = red[lane];
        #pragma unroll
        for (int o = 16; o > 0; o >>= 1)
            a += __shfl_down_sync(0xFFFFFFFFu, a, o);
        if (lane == 0) g_partial[b] = a * (1.0f / (NPTS + 1));
    }

    // ---- fused deterministic final reduction in the last block ----
    if (t == 0) {
        __threadfence();
        int ticket = atomicAdd(&g_count, 1);
        is_last = (ticket == (int)gridDim.x - 1) ? 1 : 0;
    }
    __syncthreads();
    if (is_last) {
        float a = __ldcg(&g_partial[t]) + __ldcg(&g_partial[t + TPB]);
        #pragma unroll
        for (int o = 16; o > 0; o >>= 1)
            a += __shfl_down_sync(0xFFFFFFFFu, a, o);
        if (lane == 0) red[warp] = a;
        __syncthreads();
        if (warp == 0) {
            float v = red[lane];
            #pragma unroll
            for (int o = 16; o > 0; o >>= 1)
                v += __shfl_down_sync(0xFFFFFFFFu, v, o);
            if (lane == 0) {
                out[0] = v;
                atomicExch(&g_count, 0);   // reset for next graph replay
            }
        }
    }
}

extern "C" void kernel_launch(void* const* d_in, const int* in_sizes, int n_in,
                              void* d_out, int out_size)
{
    const float* o3 = (const float*)d_in[0];  // origin_3D        (B,3,1)
    const float* s3 = (const float*)d_in[1];  // spherical_3D     (B,3,N)
    const float* o2 = (const float*)d_in[2];  // origin_2D        (B,3,1)
    const float* s2 = (const float*)d_in[3];  // spherical_2D     (B,3,N)
    const float* df = (const float*)d_in[4];  // deformation_field(B,2,N)
    float* out = (float*)d_out;

    mpd_fused_kernel<<<BATCH, TPB>>>(o3, s3, o2, s2, df, out);
}